// round 3
// baseline (speedup 1.0000x reference)
#include <cuda_runtime.h>
#include <math.h>

// Shapes (fixed):
//   segin:   [2, 4, 96, 160, 160] f32
//   edgein:  [2, 1, 96, 160, 160] f32
//   segmask: [2, 1, 96, 160, 160] i32 (0..3)
//   edgemask:[2, 1, 96, 160, 160] i32 (0..1)
// Output: float[2] = (region_loss, edge_loss)

#define NCLASS  4
#define SPATIAL 2457600               // 96*160*160
#define NBATCH  2
#define SV      (SPATIAL / 4)         // 614400 float4s per (n, channel)
#define TOTV    (NBATCH * SV)         // 1228800 vec4 voxel-groups
#define NBLK    592                   // 148 SMs x 4 (resident: 3/SM -> ~1.33 waves of blocks, fine)
#define NTHR    256
#define NITER   8                     // 592*256*8 = 1212416
#define TAIL    (TOTV - NBLK * NTHR * NITER)   // 16384

// Per-block partials:
// [0..3] intersect[c], [4..7] sumprob[c], [8..11] cnt[c],
// [12] bceP, [13] bceN, [14] posN, [15] negN
__device__ float g_part[NBLK][16];
__device__ int   g_done = 0;

__inline__ __device__ float wredf(float v) {
    #pragma unroll
    for (int o = 16; o > 0; o >>= 1) v += __shfl_down_sync(0xffffffffu, v, o);
    return v;
}
__inline__ __device__ int wredi(int v) {
    #pragma unroll
    for (int o = 16; o > 0; o >>= 1) v += __shfl_down_sync(0xffffffffu, v, o);
    return v;
}

__global__ void __launch_bounds__(NTHR, 3)
fused_loss_kernel(const float4* __restrict__ seg,
                  const float4* __restrict__ edge,
                  const int4*   __restrict__ smask,
                  const int4*   __restrict__ emask,
                  float* __restrict__ out)
{
    float in0 = 0.f, in1 = 0.f, in2 = 0.f, in3 = 0.f;   // intersect per class
    float sp0 = 0.f, sp1 = 0.f, sp2 = 0.f, sp3 = 0.f;   // sum prob per class
    float bp  = 0.f, bn  = 0.f;                          // bce pos/neg buckets
    int   pk  = 0;                                       // byte-packed class counts
    int   pos = 0;                                       // edge positives

    const int gid    = blockIdx.x * NTHR + threadIdx.x;
    const int stride = NBLK * NTHR;

    // -------- pipelined main loop: exactly NITER iterations/thread --------
    #define LOADV(vv, a0, a1, a2, a3, mt, me, mm) do {                       \
        int _b = ((vv) >= SV) ? (vv) + 3 * SV : (vv);                        \
        a0 = __ldcs(seg + _b);                                               \
        a1 = __ldcs(seg + _b + SV);                                          \
        a2 = __ldcs(seg + _b + 2 * SV);                                      \
        a3 = __ldcs(seg + _b + 3 * SV);                                      \
        mt = __ldcs(smask + (vv));                                           \
        me = __ldcs(edge + (vv));                                            \
        mm = __ldcs(emask + (vv));                                           \
    } while (0)

    #define VOX(x0, x1, x2, x3, t, ex, eti) do {                             \
        float e0 = __expf(x0);                                               \
        float e1 = __expf(x1);                                               \
        float e2 = __expf(x2);                                               \
        float e3 = __expf(x3);                                               \
        float inv = __fdividef(1.0f, e0 + e1 + e2 + e3);                     \
        float p0 = e0 * inv, p1 = e1 * inv, p2 = e2 * inv, p3 = e3 * inv;    \
        sp0 += p0; sp1 += p1; sp2 += p2; sp3 += p3;                          \
        in0 += ((t) == 0) ? p0 : 0.f;                                        \
        in1 += ((t) == 1) ? p1 : 0.f;                                        \
        in2 += ((t) == 2) ? p2 : 0.f;                                        \
        in3 += ((t) == 3) ? p3 : 0.f;                                        \
        pk  += 1 << ((t) * 8);                                               \
        float ax = fabsf(ex);                                                \
        float b  = fmaxf((ex), 0.f) - (ex) * (float)(eti)                    \
                   + __logf(1.0f + __expf(-ax));                             \
        bp += (eti) ? b : 0.f;                                               \
        bn += (eti) ? 0.f : b;                                               \
        pos += (eti);                                                        \
    } while (0)

    #define PROC(a0, a1, a2, a3, mt, me, mm) do {                            \
        VOX(a0.x, a1.x, a2.x, a3.x, mt.x, me.x, mm.x);                       \
        VOX(a0.y, a1.y, a2.y, a3.y, mt.y, me.y, mm.y);                       \
        VOX(a0.z, a1.z, a2.z, a3.z, mt.z, me.z, mm.z);                       \
        VOX(a0.w, a1.w, a2.w, a3.w, mt.w, me.w, mm.w);                       \
    } while (0)

    {
        float4 c0, c1, c2, c3, ee;
        int4   tt, et;
        int v = gid;
        LOADV(v, c0, c1, c2, c3, tt, ee, et);
        #pragma unroll
        for (int i = 0; i < NITER - 1; i++) {
            int vn = v + stride;
            float4 d0, d1, d2, d3, fe;
            int4   st, se;
            LOADV(vn, d0, d1, d2, d3, st, fe, se);   // prefetch next iter
            PROC(c0, c1, c2, c3, tt, ee, et);        // process current
            c0 = d0; c1 = d1; c2 = d2; c3 = d3;
            tt = st; ee = fe; et = se;
            v = vn;
        }
        PROC(c0, c1, c2, c3, tt, ee, et);
    }

    // tail: last TAIL vec4s, one each for global threads < TAIL
    if (gid < TAIL) {
        float4 c0, c1, c2, c3, ee;
        int4   tt, et;
        int v = TOTV - TAIL + gid;
        LOADV(v, c0, c1, c2, c3, tt, ee, et);
        PROC(c0, c1, c2, c3, tt, ee, et);
    }
    #undef LOADV
    #undef VOX
    #undef PROC

    // ---- block reduction ----
    in0 = wredf(in0); in1 = wredf(in1); in2 = wredf(in2); in3 = wredf(in3);
    sp0 = wredf(sp0); sp1 = wredf(sp1); sp2 = wredf(sp2); sp3 = wredf(sp3);
    bp  = wredf(bp);  bn  = wredf(bn);
    int c0i =  pk        & 255;
    int c1i = (pk >> 8)  & 255;
    int c2i = (pk >> 16) & 255;
    int c3i = (pk >> 24) & 255;
    c0i = wredi(c0i); c1i = wredi(c1i); c2i = wredi(c2i); c3i = wredi(c3i);
    pos = wredi(pos);

    __shared__ float sf[16];
    if (threadIdx.x < 16) sf[threadIdx.x] = 0.f;
    __syncthreads();
    if ((threadIdx.x & 31) == 0) {
        atomicAdd(&sf[0],  in0); atomicAdd(&sf[1],  in1);
        atomicAdd(&sf[2],  in2); atomicAdd(&sf[3],  in3);
        atomicAdd(&sf[4],  sp0); atomicAdd(&sf[5],  sp1);
        atomicAdd(&sf[6],  sp2); atomicAdd(&sf[7],  sp3);
        atomicAdd(&sf[8],  (float)c0i); atomicAdd(&sf[9],  (float)c1i);
        atomicAdd(&sf[10], (float)c2i); atomicAdd(&sf[11], (float)c3i);
        atomicAdd(&sf[12], bp); atomicAdd(&sf[13], bn);
        atomicAdd(&sf[14], (float)pos);
        atomicAdd(&sf[15], (float)(c0i + c1i + c2i + c3i - pos)); // negN
    }
    __syncthreads();
    if (threadIdx.x < 16) g_part[blockIdx.x][threadIdx.x] = sf[threadIdx.x];
    __threadfence();

    __shared__ int sdone;
    if (threadIdx.x == 0) sdone = atomicAdd(&g_done, 1);
    __syncthreads();

    if (sdone == NBLK - 1) {
        __threadfence();
        int c  = threadIdx.x & 15;
        int r0 = threadIdx.x >> 4;
        double s = 0.0;
        for (int r = r0; r < NBLK; r += 16) s += (double)g_part[r][c];
        __shared__ double red[NTHR];
        red[threadIdx.x] = s;
        __syncthreads();
        if (threadIdx.x < 16) {
            double tot = 0.0;
            #pragma unroll
            for (int k = 0; k < 16; k++) tot += red[c + 16 * k];
            red[threadIdx.x] = tot;
        }
        __syncthreads();
        if (threadIdx.x == 0) {
            const double smooth = 1e-5;
            double dsum = 0.0;
            #pragma unroll
            for (int cc = 0; cc < NCLASS; cc++) {
                double I = red[cc], P = red[4 + cc], T = red[8 + cc];
                dsum += (2.0 * I + smooth) / (P + T + smooth);
            }
            out[0] = (float)(1.0 - dsum / (double)NCLASS);

            double pn = red[14], nn = red[15], tt = pn + nn;
            out[1] = (float)((nn * red[12] + pn * red[13]) / (tt * tt));

            g_done = 0;   // reset for next graph replay
        }
    }
}

extern "C" void kernel_launch(void* const* d_in, const int* in_sizes, int n_in,
                              void* d_out, int out_size) {
    const float4* seg   = (const float4*)d_in[0];
    const float4* edge  = (const float4*)d_in[1];
    const int4*   smask = (const int4*)d_in[2];
    const int4*   emask = (const int4*)d_in[3];
    float* out = (float*)d_out;

    fused_loss_kernel<<<NBLK, NTHR>>>(seg, edge, smask, emask, out);
}

// round 4
// speedup vs baseline: 1.0066x; 1.0066x over previous
#include <cuda_runtime.h>
#include <math.h>

// Shapes (fixed):
//   segin:   [2, 4, 96, 160, 160] f32
//   edgein:  [2, 1, 96, 160, 160] f32
//   segmask: [2, 1, 96, 160, 160] i32 (0..3)
//   edgemask:[2, 1, 96, 160, 160] i32 (0..1)
// Output: float[2] = (region_loss, edge_loss)

#define NCLASS  4
#define SPATIAL 2457600               // 96*160*160
#define NBATCH  2
#define SV      (SPATIAL / 4)         // 614400 float4s per (n, channel)
#define TOTV    (NBATCH * SV)         // 1228800 vec4 voxel-groups
#define NBLK    592                   // 148 SMs x 4 (resident: 3/SM -> ~1.33 waves of blocks, fine)
#define NTHR    256
#define NITER   8                     // 592*256*8 = 1212416
#define TAIL    (TOTV - NBLK * NTHR * NITER)   // 16384

// Per-block partials:
// [0..3] intersect[c], [4..7] sumprob[c], [8..11] cnt[c],
// [12] bceP, [13] bceN, [14] posN, [15] negN
__device__ float g_part[NBLK][16];
__device__ int   g_done = 0;

__inline__ __device__ float wredf(float v) {
    #pragma unroll
    for (int o = 16; o > 0; o >>= 1) v += __shfl_down_sync(0xffffffffu, v, o);
    return v;
}
__inline__ __device__ int wredi(int v) {
    #pragma unroll
    for (int o = 16; o > 0; o >>= 1) v += __shfl_down_sync(0xffffffffu, v, o);
    return v;
}

__global__ void __launch_bounds__(NTHR, 3)
fused_loss_kernel(const float4* __restrict__ seg,
                  const float4* __restrict__ edge,
                  const int4*   __restrict__ smask,
                  const int4*   __restrict__ emask,
                  float* __restrict__ out)
{
    float in0 = 0.f, in1 = 0.f, in2 = 0.f, in3 = 0.f;   // intersect per class
    float sp0 = 0.f, sp1 = 0.f, sp2 = 0.f, sp3 = 0.f;   // sum prob per class
    float bp  = 0.f, bn  = 0.f;                          // bce pos/neg buckets
    int   pk  = 0;                                       // byte-packed class counts
    int   pos = 0;                                       // edge positives

    const int gid    = blockIdx.x * NTHR + threadIdx.x;
    const int stride = NBLK * NTHR;

    // -------- pipelined main loop: exactly NITER iterations/thread --------
    #define LOADV(vv, a0, a1, a2, a3, mt, me, mm) do {                       \
        int _b = ((vv) >= SV) ? (vv) + 3 * SV : (vv);                        \
        a0 = __ldcs(seg + _b);                                               \
        a1 = __ldcs(seg + _b + SV);                                          \
        a2 = __ldcs(seg + _b + 2 * SV);                                      \
        a3 = __ldcs(seg + _b + 3 * SV);                                      \
        mt = __ldcs(smask + (vv));                                           \
        me = __ldcs(edge + (vv));                                            \
        mm = __ldcs(emask + (vv));                                           \
    } while (0)

    #define VOX(x0, x1, x2, x3, t, ex, eti) do {                             \
        float e0 = __expf(x0);                                               \
        float e1 = __expf(x1);                                               \
        float e2 = __expf(x2);                                               \
        float e3 = __expf(x3);                                               \
        float inv = __fdividef(1.0f, e0 + e1 + e2 + e3);                     \
        float p0 = e0 * inv, p1 = e1 * inv, p2 = e2 * inv, p3 = e3 * inv;    \
        sp0 += p0; sp1 += p1; sp2 += p2; sp3 += p3;                          \
        in0 += ((t) == 0) ? p0 : 0.f;                                        \
        in1 += ((t) == 1) ? p1 : 0.f;                                        \
        in2 += ((t) == 2) ? p2 : 0.f;                                        \
        in3 += ((t) == 3) ? p3 : 0.f;                                        \
        pk  += 1 << ((t) * 8);                                               \
        float ax = fabsf(ex);                                                \
        float b  = fmaxf((ex), 0.f) - (ex) * (float)(eti)                    \
                   + __logf(1.0f + __expf(-ax));                             \
        bp += (eti) ? b : 0.f;                                               \
        bn += (eti) ? 0.f : b;                                               \
        pos += (eti);                                                        \
    } while (0)

    #define PROC(a0, a1, a2, a3, mt, me, mm) do {                            \
        VOX(a0.x, a1.x, a2.x, a3.x, mt.x, me.x, mm.x);                       \
        VOX(a0.y, a1.y, a2.y, a3.y, mt.y, me.y, mm.y);                       \
        VOX(a0.z, a1.z, a2.z, a3.z, mt.z, me.z, mm.z);                       \
        VOX(a0.w, a1.w, a2.w, a3.w, mt.w, me.w, mm.w);                       \
    } while (0)

    {
        float4 c0, c1, c2, c3, ee;
        int4   tt, et;
        int v = gid;
        LOADV(v, c0, c1, c2, c3, tt, ee, et);
        #pragma unroll
        for (int i = 0; i < NITER - 1; i++) {
            int vn = v + stride;
            float4 d0, d1, d2, d3, fe;
            int4   st, se;
            LOADV(vn, d0, d1, d2, d3, st, fe, se);   // prefetch next iter
            PROC(c0, c1, c2, c3, tt, ee, et);        // process current
            c0 = d0; c1 = d1; c2 = d2; c3 = d3;
            tt = st; ee = fe; et = se;
            v = vn;
        }
        PROC(c0, c1, c2, c3, tt, ee, et);
    }

    // tail: last TAIL vec4s, one each for global threads < TAIL
    if (gid < TAIL) {
        float4 c0, c1, c2, c3, ee;
        int4   tt, et;
        int v = TOTV - TAIL + gid;
        LOADV(v, c0, c1, c2, c3, tt, ee, et);
        PROC(c0, c1, c2, c3, tt, ee, et);
    }
    #undef LOADV
    #undef VOX
    #undef PROC

    // ---- block reduction ----
    in0 = wredf(in0); in1 = wredf(in1); in2 = wredf(in2); in3 = wredf(in3);
    sp0 = wredf(sp0); sp1 = wredf(sp1); sp2 = wredf(sp2); sp3 = wredf(sp3);
    bp  = wredf(bp);  bn  = wredf(bn);
    int c0i =  pk        & 255;
    int c1i = (pk >> 8)  & 255;
    int c2i = (pk >> 16) & 255;
    int c3i = (pk >> 24) & 255;
    c0i = wredi(c0i); c1i = wredi(c1i); c2i = wredi(c2i); c3i = wredi(c3i);
    pos = wredi(pos);

    __shared__ float sf[16];
    if (threadIdx.x < 16) sf[threadIdx.x] = 0.f;
    __syncthreads();
    if ((threadIdx.x & 31) == 0) {
        atomicAdd(&sf[0],  in0); atomicAdd(&sf[1],  in1);
        atomicAdd(&sf[2],  in2); atomicAdd(&sf[3],  in3);
        atomicAdd(&sf[4],  sp0); atomicAdd(&sf[5],  sp1);
        atomicAdd(&sf[6],  sp2); atomicAdd(&sf[7],  sp3);
        atomicAdd(&sf[8],  (float)c0i); atomicAdd(&sf[9],  (float)c1i);
        atomicAdd(&sf[10], (float)c2i); atomicAdd(&sf[11], (float)c3i);
        atomicAdd(&sf[12], bp); atomicAdd(&sf[13], bn);
        atomicAdd(&sf[14], (float)pos);
        atomicAdd(&sf[15], (float)(c0i + c1i + c2i + c3i - pos)); // negN
    }
    __syncthreads();
    if (threadIdx.x < 16) g_part[blockIdx.x][threadIdx.x] = sf[threadIdx.x];
    __threadfence();

    __shared__ int sdone;
    if (threadIdx.x == 0) sdone = atomicAdd(&g_done, 1);
    __syncthreads();

    if (sdone == NBLK - 1) {
        __threadfence();
        int c  = threadIdx.x & 15;
        int r0 = threadIdx.x >> 4;
        double s = 0.0;
        for (int r = r0; r < NBLK; r += 16) s += (double)g_part[r][c];
        __shared__ double red[NTHR];
        red[threadIdx.x] = s;
        __syncthreads();
        if (threadIdx.x < 16) {
            double tot = 0.0;
            #pragma unroll
            for (int k = 0; k < 16; k++) tot += red[c + 16 * k];
            red[threadIdx.x] = tot;
        }
        __syncthreads();
        if (threadIdx.x == 0) {
            const double smooth = 1e-5;
            double dsum = 0.0;
            #pragma unroll
            for (int cc = 0; cc < NCLASS; cc++) {
                double I = red[cc], P = red[4 + cc], T = red[8 + cc];
                dsum += (2.0 * I + smooth) / (P + T + smooth);
            }
            out[0] = (float)(1.0 - dsum / (double)NCLASS);

            double pn = red[14], nn = red[15], tt = pn + nn;
            out[1] = (float)((nn * red[12] + pn * red[13]) / (tt * tt));

            g_done = 0;   // reset for next graph replay
        }
    }
}

extern "C" void kernel_launch(void* const* d_in, const int* in_sizes, int n_in,
                              void* d_out, int out_size) {
    const float4* seg   = (const float4*)d_in[0];
    const float4* edge  = (const float4*)d_in[1];
    const int4*   smask = (const int4*)d_in[2];
    const int4*   emask = (const int4*)d_in[3];
    float* out = (float*)d_out;

    fused_loss_kernel<<<NBLK, NTHR>>>(seg, edge, smask, emask, out);
}